// round 5
// baseline (speedup 1.0000x reference)
#include <cuda_runtime.h>
#include <cstdint>

// Problem constants
#define B_TOT   4096
#define S_DIM   64
#define H_DIM   64
#define N_SEL   4
#define ATT_DIM 128
#define P_DIM   64

#define G_PER_BLK 4
#define NBLKS (B_TOT / G_PER_BLK)        // 1024
#define PITCH 68                          // smem row pitch (floats): 16B aligned, conflict-free

// Output layout (flatten-concat of reference return tuple, float32):
//   [0,            1048576)  proto_st  (B,N,H)
//   [1048576,      2097152)  residuals (B,N,H)
//   [2097152]                loss (scalar)
//   [2097153,      2113537)  indexes (B,N) cast to float
#define OFF_RES  1048576u
#define OFF_LOSS 2097152u
#define OFF_IDX  2097153u

// Scratch (no allocations allowed -> device globals)
__device__ __align__(16) float g_M[N_SEL * H_DIM * H_DIM];  // M[n][h][k] = sum_a Wq[n,a,h]*Wk[n,a,k]
__device__ __align__(16) float g_pe[S_DIM * H_DIM];
__device__ float g_partial[NBLKS];

// ---------------------------------------------------------------------------
// Prep: positional encoding, mimicking numpy float32 intermediate rounding:
//   div = exp(f32(h_even) * f32(-ln(1e4)/64))   (rounded to f32)
//   pe  = sin/cos(f32(s) * div)
// exp/sin/cos evaluated in double then rounded (numpy libm is <1ulp).
// ---------------------------------------------------------------------------
__global__ void pe_kernel() {
    int s = blockIdx.x;     // 64
    int h = threadIdx.x;    // 64
    const float c = (float)(-0.14391156056944368);   // f32(-ln(10000)/64)
    float arg  = (float)(h & ~1) * c;                // f32 multiply
    float divf = (float)exp((double)arg);            // f32 exp result
    float ang  = (float)s * divf;                    // f32 multiply
    double sv  = (h & 1) ? cos((double)ang) : sin((double)ang);
    g_pe[s * H_DIM + h] = (float)sv;
}

// ---------------------------------------------------------------------------
// Prep: M[n] = Wq_n^T @ Wk_n   (4 x 64 x 64)
// grid 256 = (n*64+h), 64 threads = k
// ---------------------------------------------------------------------------
__global__ void m_kernel(const float* __restrict__ Wq, const float* __restrict__ Wk) {
    int nh = blockIdx.x;
    int k  = threadIdx.x;
    int n  = nh >> 6;
    int h  = nh & 63;
    const float* wq = Wq + (size_t)n * ATT_DIM * H_DIM + h;   // stride 64
    const float* wk = Wk + (size_t)n * ATT_DIM * H_DIM + k;   // stride 64
    float acc = 0.f;
#pragma unroll 8
    for (int a = 0; a < ATT_DIM; ++a)
        acc += wq[a * H_DIM] * wk[a * H_DIM];
    g_M[nh * 64 + k] = acc;
}

// ---------------------------------------------------------------------------
// threefry2x32, JAX *partitionable* mode (default since jax 0.4.30):
// per-element 64-bit counter i -> block (x0, x1) = (hi32(i), lo32(i)) = (0, gi)
// key = jax.random.key(1) -> (k0, k1) = (0, 1); ks = [0, 1, 0x1BD11BDB]
// 32-bit draw = out0 ^ out1  (lax.convert_element_type(bits1 ^ bits2, uint32))
// ---------------------------------------------------------------------------
__device__ __forceinline__ uint32_t rotl32(uint32_t x, int d) {
    return (x << d) | (x >> (32 - d));
}

__device__ __forceinline__ float gumbel_at(uint32_t gi) {
    const uint32_t k0 = 0u, k1 = 1u, k2 = 0x1BD11BDBu;  // 0 ^ 1 ^ 0x1BD11BDA
    uint32_t x0 = 0u + k0;     // counts_hi = 0 (total size 2^20 < 2^32)
    uint32_t x1 = gi + k1;     // counts_lo = flat index in (B,N,S)

#define TF_ROUND(r) { x0 += x1; x1 = rotl32(x1, (r)); x1 ^= x0; }
    TF_ROUND(13) TF_ROUND(15) TF_ROUND(26) TF_ROUND(6)
    x0 += k1; x1 += k2 + 1u;
    TF_ROUND(17) TF_ROUND(29) TF_ROUND(16) TF_ROUND(24)
    x0 += k2; x1 += k0 + 2u;
    TF_ROUND(13) TF_ROUND(15) TF_ROUND(26) TF_ROUND(6)
    x0 += k0; x1 += k1 + 3u;
    TF_ROUND(17) TF_ROUND(29) TF_ROUND(16) TF_ROUND(24)
    x0 += k1; x1 += k2 + 4u;
    TF_ROUND(13) TF_ROUND(15) TF_ROUND(26) TF_ROUND(6)
    x0 += k2; x1 += k0 + 5u;
#undef TF_ROUND

    uint32_t bits = x0 ^ x1;                        // partitionable 32-bit combine
    uint32_t fb = (bits >> 9) | 0x3f800000u;
    float u = __uint_as_float(fb) - 1.0f;           // [0,1)
    u = fmaxf(u, 1.17549435e-38f);                  // jax uniform(minval=tiny)
    return -logf(-logf(u));
}

// ---------------------------------------------------------------------------
// Main fused kernel: 1024 blocks x 256 threads, 4 batches per block.
// smem (floats): xs[4][64][68] pos | pros[64][68] | vs[4][4][64] |
//                score[256] | red[256] | xselb[256]
// ---------------------------------------------------------------------------
#define SMEM_FLOATS (G_PER_BLK*S_DIM*PITCH + P_DIM*PITCH + G_PER_BLK*N_SEL*64 + 256 + 256 + 256)
#define SMEM_BYTES  (SMEM_FLOATS * 4)

__global__ void __launch_bounds__(256, 2) main_kernel(
    const float* __restrict__ x,
    const float* __restrict__ prototypes,
    float* __restrict__ out)
{
    extern __shared__ float sm[];
    float* xs    = sm;                                  // pos tiles
    float* pros  = xs + G_PER_BLK * S_DIM * PITCH;
    float* vs    = pros + P_DIM * PITCH;                // [g][n][64]
    float* score = vs + G_PER_BLK * N_SEL * 64;         // [256]
    float* red   = score + 256;                          // psum, then loss reduce
    float* xselb = red + 256;                            // selected raw x rows [n][64]
    __shared__ int isel[2 * N_SEL];                      // [0..3]=sel s, [4..7]=proto idx

    const int tid = threadIdx.x;
    const int b0  = blockIdx.x * G_PER_BLK;
    const int n   = tid >> 6;      // head for per-(n,*) phases
    const int ss  = tid & 63;      // s / p / h depending on phase

    // --- stage prototypes (float4, pitch 68) ---
    {
        const float4* pp4 = reinterpret_cast<const float4*>(prototypes);
        for (int i4 = tid; i4 < P_DIM * H_DIM / 4; i4 += 256) {
            int p  = i4 >> 4;
            int k4 = i4 & 15;
            *reinterpret_cast<float4*>(&pros[p * PITCH + k4 * 4]) = pp4[i4];
        }
    }
    // --- stage pos = x + pe (float4) ---
    {
        const float4* xb4 = reinterpret_cast<const float4*>(x + (size_t)b0 * S_DIM * H_DIM);
        const float4* pe4 = reinterpret_cast<const float4*>(g_pe);
        for (int i4 = tid; i4 < G_PER_BLK * S_DIM * H_DIM / 4; i4 += 256) {
            int g  = i4 >> 10;
            int s  = (i4 >> 4) & 63;
            int h4 = i4 & 15;
            float4 xv = xb4[i4];
            float4 pv = pe4[i4 & 1023];
            float4 o;
            o.x = xv.x + pv.x; o.y = xv.y + pv.y;
            o.z = xv.z + pv.z; o.w = xv.w + pv.w;
            *reinterpret_cast<float4*>(&xs[(g * 64 + s) * PITCH + h4 * 4]) = o;
        }
    }
    __syncthreads();

    // --- psum[g][h] = sum_s pos[g][s][h]   (tid -> g=tid>>6, h=tid&63) ---
    {
        int g = tid >> 6, h = tid & 63;
        float ps = 0.f;
#pragma unroll
        for (int s = 0; s < S_DIM; ++s)
            ps += xs[(g * 64 + s) * PITCH + h];
        red[tid] = ps;
    }
    __syncthreads();

    // --- v[g][n][h] = (M[n][h][:] . psum[g][:]) / 512   (tid -> n,h) ---
    {
        const float4* Mrow4 = reinterpret_cast<const float4*>(g_M + (size_t)(n * 64 + ss) * 64);
        float a0 = 0.f, a1 = 0.f, a2 = 0.f, a3 = 0.f;
#pragma unroll 4
        for (int k4 = 0; k4 < 16; ++k4) {
            float4 m  = Mrow4[k4];
            float4 r0 = *reinterpret_cast<const float4*>(&red[k4 * 4]);
            float4 r1 = *reinterpret_cast<const float4*>(&red[64 + k4 * 4]);
            float4 r2 = *reinterpret_cast<const float4*>(&red[128 + k4 * 4]);
            float4 r3 = *reinterpret_cast<const float4*>(&red[192 + k4 * 4]);
            a0 += m.x * r0.x + m.y * r0.y + m.z * r0.z + m.w * r0.w;
            a1 += m.x * r1.x + m.y * r1.y + m.z * r1.z + m.w * r1.w;
            a2 += m.x * r2.x + m.y * r2.y + m.z * r2.z + m.w * r2.w;
            a3 += m.x * r3.x + m.y * r3.y + m.z * r3.z + m.w * r3.w;
        }
        const float sc = 1.0f / 512.0f;
        vs[(0 * N_SEL + n) * 64 + ss] = a0 * sc;
        vs[(1 * N_SEL + n) * 64 + ss] = a1 * sc;
        vs[(2 * N_SEL + n) * 64 + ss] = a2 * sc;
        vs[(3 * N_SEL + n) * 64 + ss] = a3 * sc;
    }
    __syncthreads();

    float losspart = 0.f;

    for (int g = 0; g < G_PER_BLK; ++g) {
        // --- logits[n][s] + gumbel ---
        {
            const float4* pr4 = reinterpret_cast<const float4*>(&xs[(g * 64 + ss) * PITCH]);
            const float4* vr4 = reinterpret_cast<const float4*>(&vs[(g * N_SEL + n) * 64]);
            float lg = 0.f;
#pragma unroll
            for (int h4 = 0; h4 < 16; ++h4) {
                float4 a = pr4[h4], b = vr4[h4];
                lg += a.x * b.x + a.y * b.y + a.z * b.z + a.w * b.w;
            }
            uint32_t gi = (uint32_t)(b0 + g) * 256u + (uint32_t)tid;
            score[tid] = lg + gumbel_at(gi);
        }
        __syncthreads();
        if (tid < N_SEL) {   // argmax over s (first-max, matches jnp.argmax)
            float best = score[tid * 64];
            int bi = 0;
            for (int s2 = 1; s2 < S_DIM; ++s2) {
                float v2 = score[tid * 64 + s2];
                if (v2 > best) { best = v2; bi = s2; }
            }
            isel[tid] = bi;
        }
        __syncthreads();

        // --- fetch selected RAW x rows (exact x_sel) ---
        xselb[tid] = x[((size_t)(b0 + g) * S_DIM + isel[n]) * H_DIM + ss];
        __syncthreads();

        // --- VQ distances: d2_rel[n][p] = sum_k p*(p - 2x) ---
        {
            const float4* prow4 = reinterpret_cast<const float4*>(&pros[ss * PITCH]);
            const float4* xr4   = reinterpret_cast<const float4*>(&xselb[n * 64]);
            float d = 0.f;
#pragma unroll
            for (int k4 = 0; k4 < 16; ++k4) {
                float4 pv = prow4[k4], xv = xr4[k4];
                d += pv.x * (pv.x - 2.0f * xv.x);
                d += pv.y * (pv.y - 2.0f * xv.y);
                d += pv.z * (pv.z - 2.0f * xv.z);
                d += pv.w * (pv.w - 2.0f * xv.w);
            }
            score[tid] = d;
        }
        __syncthreads();
        if (tid < N_SEL) {   // argmin over p (first-min, matches jnp.argmin)
            float best = score[tid * 64];
            int bi = 0;
            for (int p2 = 1; p2 < P_DIM; ++p2) {
                float v2 = score[tid * 64 + p2];
                if (v2 < best) { best = v2; bi = p2; }
            }
            isel[N_SEL + tid] = bi;
            out[OFF_IDX + (size_t)(b0 + g) * N_SEL + tid] = (float)isel[tid];
        }
        __syncthreads();

        // --- outputs: proto_st / residuals (mimic reference rounding) ---
        {
            float xv  = xselb[tid];
            float pv  = pros[isel[N_SEL + n] * PITCH + ss];
            float d   = pv - xv;        // stop_grad(proto - x_sel)
            float pst = xv + d;         // proto_st
            size_t ob = (size_t)(b0 + g) * 256 + tid;
            out[ob]           = pst;
            out[OFF_RES + ob] = xv - pst;
            losspart += d * d;
        }
        __syncthreads();   // xselb/score reused next iteration
    }

    // deterministic block loss reduction
    red[tid] = losspart;
    __syncthreads();
#pragma unroll
    for (int st = 128; st > 0; st >>= 1) {
        if (tid < st) red[tid] += red[tid + st];
        __syncthreads();
    }
    if (tid == 0) g_partial[blockIdx.x] = red[0];
}

// ---------------------------------------------------------------------------
// Deterministic final loss: loss = 1.25 * mean((proto - x_sel)^2)
// ---------------------------------------------------------------------------
__global__ void loss_kernel(float* __restrict__ out) {
    __shared__ float red[256];
    int tid = threadIdx.x;
    float s = 0.f;
    for (int i = tid; i < NBLKS; i += 256)   // fixed order -> deterministic
        s += g_partial[i];
    red[tid] = s;
    __syncthreads();
#pragma unroll
    for (int st = 128; st > 0; st >>= 1) {
        if (tid < st) red[tid] += red[tid + st];
        __syncthreads();
    }
    if (tid == 0)
        out[OFF_LOSS] = red[0] * 1.25f / (float)(B_TOT * N_SEL * H_DIM);
}

// ---------------------------------------------------------------------------
extern "C" void kernel_launch(void* const* d_in, const int* in_sizes, int n_in,
                              void* d_out, int out_size) {
    (void)in_sizes; (void)n_in; (void)out_size;
    const float* x  = (const float*)d_in[0];
    const float* Wq = (const float*)d_in[1];
    const float* Wk = (const float*)d_in[2];
    const float* pr = (const float*)d_in[3];
    float* out = (float*)d_out;

    cudaFuncSetAttribute(main_kernel,
                         cudaFuncAttributeMaxDynamicSharedMemorySize, SMEM_BYTES);

    pe_kernel<<<S_DIM, H_DIM>>>();
    m_kernel<<<N_SEL * H_DIM, H_DIM>>>(Wq, Wk);
    main_kernel<<<NBLKS, 256, SMEM_BYTES>>>(x, pr, out);
    loss_kernel<<<1, 256>>>(out);
}

// round 6
// speedup vs baseline: 1.0260x; 1.0260x over previous
#include <cuda_runtime.h>
#include <cstdint>

// Problem constants
#define B_TOT   4096
#define S_DIM   64
#define H_DIM   64
#define N_SEL   4
#define ATT_DIM 128
#define P_DIM   64

#define G_PER_BLK 4
#define NBLKS (B_TOT / G_PER_BLK)        // 1024
#define PITCH 68                          // smem row pitch (floats): 16B aligned, conflict-free

// Output layout (flatten-concat of reference return tuple, float32):
//   [0,            1048576)  proto_st  (B,N,H)
//   [1048576,      2097152)  residuals (B,N,H)
//   [2097152]                loss (scalar)
//   [2097153,      2113537)  indexes (B,N) cast to float
#define OFF_RES  1048576u
#define OFF_LOSS 2097152u
#define OFF_IDX  2097153u

// Scratch (no allocations allowed -> device globals)
__device__ __align__(16) float g_M[N_SEL * H_DIM * H_DIM];  // M[n][h][k] = sum_a Wq[n,a,h]*Wk[n,a,k]
__device__ __align__(16) float g_pe[S_DIM * H_DIM];
__device__ float g_partial[NBLKS];
__device__ unsigned int g_count;          // zero-init; last block resets -> replay-safe

// ---------------------------------------------------------------------------
// Fused prep: blocks [0,256) compute M = Wq_n^T @ Wk_n ; blocks [256,260) PE.
// ---------------------------------------------------------------------------
__global__ void prep_kernel(const float* __restrict__ Wq, const float* __restrict__ Wk) {
    if (blockIdx.x < 256) {
        int nh = blockIdx.x;
        int k  = threadIdx.x;
        int n  = nh >> 6;
        int h  = nh & 63;
        const float* wq = Wq + (size_t)n * ATT_DIM * H_DIM + h;   // stride 64 (broadcast per block)
        const float* wk = Wk + (size_t)n * ATT_DIM * H_DIM + k;   // stride 64 (coalesced)
        float acc = 0.f;
#pragma unroll 8
        for (int a = 0; a < ATT_DIM; ++a)
            acc += wq[a * H_DIM] * wk[a * H_DIM];
        g_M[nh * 64 + k] = acc;
    } else {
        // PE mimicking numpy f32 intermediate rounding:
        //   div = f32(exp(f32(h_even) * f32(-ln 1e4/64))); pe = sin/cos(f32(s)*div)
        int base = (blockIdx.x - 256) * 1024;    // 4 blocks x 1024 elems
        const float c = (float)(-0.14391156056944368);
#pragma unroll
        for (int k = 0; k < 16; ++k) {
            int idx = base + k * 64 + threadIdx.x;
            int s = idx >> 6, h = idx & 63;
            float arg  = (float)(h & ~1) * c;
            float divf = (float)exp((double)arg);
            float ang  = (float)s * divf;
            double sv  = (h & 1) ? cos((double)ang) : sin((double)ang);
            g_pe[idx] = (float)sv;
        }
    }
}

// ---------------------------------------------------------------------------
// threefry2x32, JAX partitionable mode: counter i -> (x0,x1)=(0,gi), key (0,1)
// 32-bit draw = out0 ^ out1; then jax uniform -> gumbel (bit-fidelity critical)
// ---------------------------------------------------------------------------
__device__ __forceinline__ uint32_t rotl32(uint32_t x, int d) {
    return (x << d) | (x >> (32 - d));
}

__device__ __forceinline__ float gumbel_at(uint32_t gi) {
    const uint32_t k0 = 0u, k1 = 1u, k2 = 0x1BD11BDBu;  // 0 ^ 1 ^ 0x1BD11BDA
    uint32_t x0 = 0u + k0;
    uint32_t x1 = gi + k1;

#define TF_ROUND(r) { x0 += x1; x1 = rotl32(x1, (r)); x1 ^= x0; }
    TF_ROUND(13) TF_ROUND(15) TF_ROUND(26) TF_ROUND(6)
    x0 += k1; x1 += k2 + 1u;
    TF_ROUND(17) TF_ROUND(29) TF_ROUND(16) TF_ROUND(24)
    x0 += k2; x1 += k0 + 2u;
    TF_ROUND(13) TF_ROUND(15) TF_ROUND(26) TF_ROUND(6)
    x0 += k0; x1 += k1 + 3u;
    TF_ROUND(17) TF_ROUND(29) TF_ROUND(16) TF_ROUND(24)
    x0 += k1; x1 += k2 + 4u;
    TF_ROUND(13) TF_ROUND(15) TF_ROUND(26) TF_ROUND(6)
    x0 += k2; x1 += k0 + 5u;
#undef TF_ROUND

    uint32_t bits = x0 ^ x1;
    uint32_t fb = (bits >> 9) | 0x3f800000u;
    float u = __uint_as_float(fb) - 1.0f;           // [0,1)
    u = fmaxf(u, 1.17549435e-38f);                  // jax uniform(minval=tiny)
    return -logf(-logf(u));                         // libdevice logf == XLA path
}

// ---------------------------------------------------------------------------
// Main fused kernel: 1024 blocks x 256 threads, 4 batches per block.
// ---------------------------------------------------------------------------
#define SMEM_FLOATS (G_PER_BLK*S_DIM*PITCH + P_DIM*PITCH + G_PER_BLK*N_SEL*64 + 256 + 256 + 256)
#define SMEM_BYTES  (SMEM_FLOATS * 4)

__global__ void __launch_bounds__(256, 2) main_kernel(
    const float* __restrict__ x,
    const float* __restrict__ prototypes,
    float* __restrict__ out)
{
    extern __shared__ float sm[];
    float* xs    = sm;                                  // pos tiles [4][64][68]
    float* pros  = xs + G_PER_BLK * S_DIM * PITCH;      // [64][68]
    float* vs    = pros + P_DIM * PITCH;                // [g][n][64]
    float* score = vs + G_PER_BLK * N_SEL * 64;         // [256]
    float* red   = score + 256;                          // psum / reductions
    float* xselb = red + 256;                            // selected raw x rows [n][64]
    __shared__ int   isel[2 * N_SEL];                    // [0..3]=sel s, [4..7]=proto idx
    __shared__ float swred[8];
    __shared__ int   swidx[8];
    __shared__ unsigned int amLast;

    const int tid = threadIdx.x;
    const int b0  = blockIdx.x * G_PER_BLK;
    const int n   = tid >> 6;
    const int ss  = tid & 63;
    const int wid = tid >> 5;

    // --- stage prototypes (float4, pitch 68) ---
    {
        const float4* pp4 = reinterpret_cast<const float4*>(prototypes);
        for (int i4 = tid; i4 < P_DIM * H_DIM / 4; i4 += 256) {
            int p  = i4 >> 4;
            int k4 = i4 & 15;
            *reinterpret_cast<float4*>(&pros[p * PITCH + k4 * 4]) = pp4[i4];
        }
    }
    // --- stage pos = x + pe (float4) ---
    {
        const float4* xb4 = reinterpret_cast<const float4*>(x + (size_t)b0 * S_DIM * H_DIM);
        const float4* pe4 = reinterpret_cast<const float4*>(g_pe);
        for (int i4 = tid; i4 < G_PER_BLK * S_DIM * H_DIM / 4; i4 += 256) {
            int g  = i4 >> 10;
            int s  = (i4 >> 4) & 63;
            int h4 = i4 & 15;
            float4 xv = xb4[i4];
            float4 pv = pe4[i4 & 1023];
            float4 o;
            o.x = xv.x + pv.x; o.y = xv.y + pv.y;
            o.z = xv.z + pv.z; o.w = xv.w + pv.w;
            *reinterpret_cast<float4*>(&xs[(g * 64 + s) * PITCH + h4 * 4]) = o;
        }
    }

    // --- all 4 gumbels per thread up front: 4 independent threefry chains
    //     (ILP) executing in the shadow of the staging LDGs ---
    float gm[G_PER_BLK];
#pragma unroll
    for (int g = 0; g < G_PER_BLK; ++g)
        gm[g] = gumbel_at((uint32_t)(b0 + g) * 256u + (uint32_t)tid);

    __syncthreads();

    // --- psum[g][h] = sum_s pos[g][s][h] ---
    {
        int g = tid >> 6, h = tid & 63;
        float ps = 0.f;
#pragma unroll
        for (int s = 0; s < S_DIM; ++s)
            ps += xs[(g * 64 + s) * PITCH + h];
        red[tid] = ps;
    }
    __syncthreads();

    // --- v[g][n][h] = (M[n][h][:] . psum[g][:]) / 512 ---
    {
        const float4* Mrow4 = reinterpret_cast<const float4*>(g_M + (size_t)(n * 64 + ss) * 64);
        float a0 = 0.f, a1 = 0.f, a2 = 0.f, a3 = 0.f;
#pragma unroll 4
        for (int k4 = 0; k4 < 16; ++k4) {
            float4 m  = Mrow4[k4];
            float4 r0 = *reinterpret_cast<const float4*>(&red[k4 * 4]);
            float4 r1 = *reinterpret_cast<const float4*>(&red[64 + k4 * 4]);
            float4 r2 = *reinterpret_cast<const float4*>(&red[128 + k4 * 4]);
            float4 r3 = *reinterpret_cast<const float4*>(&red[192 + k4 * 4]);
            a0 += m.x * r0.x + m.y * r0.y + m.z * r0.z + m.w * r0.w;
            a1 += m.x * r1.x + m.y * r1.y + m.z * r1.z + m.w * r1.w;
            a2 += m.x * r2.x + m.y * r2.y + m.z * r2.z + m.w * r2.w;
            a3 += m.x * r3.x + m.y * r3.y + m.z * r3.z + m.w * r3.w;
        }
        const float sc = 1.0f / 512.0f;
        vs[(0 * N_SEL + n) * 64 + ss] = a0 * sc;
        vs[(1 * N_SEL + n) * 64 + ss] = a1 * sc;
        vs[(2 * N_SEL + n) * 64 + ss] = a2 * sc;
        vs[(3 * N_SEL + n) * 64 + ss] = a3 * sc;
    }
    __syncthreads();

    float losspart = 0.f;

    for (int g = 0; g < G_PER_BLK; ++g) {
        // --- score[n][s] = logits + gumbel ---
        float myscore;
        {
            const float4* pr4 = reinterpret_cast<const float4*>(&xs[(g * 64 + ss) * PITCH]);
            const float4* vr4 = reinterpret_cast<const float4*>(&vs[(g * N_SEL + n) * 64]);
            float lg = 0.f;
#pragma unroll
            for (int h4 = 0; h4 < 16; ++h4) {
                float4 a = pr4[h4], b = vr4[h4];
                lg += a.x * b.x + a.y * b.y + a.z * b.z + a.w * b.w;
            }
            myscore = lg + gm[g];
        }

        // --- parallel argmax over s (first-max tie-break, matches jnp.argmax) ---
        {
            float v = myscore; int idx = ss;
#pragma unroll
            for (int off = 16; off > 0; off >>= 1) {
                float ov = __shfl_xor_sync(0xFFFFFFFFu, v, off);
                int   oi = __shfl_xor_sync(0xFFFFFFFFu, idx, off);
                if (ov > v || (ov == v && oi < idx)) { v = ov; idx = oi; }
            }
            if ((tid & 31) == 0) { swred[wid] = v; swidx[wid] = idx; }
        }
        __syncthreads();
        if (tid < N_SEL) {
            float va = swred[2 * tid];     int ia = swidx[2 * tid];
            float vb = swred[2 * tid + 1]; int ib = swidx[2 * tid + 1];
            int sel = (vb > va || (vb == va && ib < ia)) ? ib : ia;
            isel[tid] = sel;
            out[OFF_IDX + (size_t)(b0 + g) * N_SEL + tid] = (float)sel;
        }
        __syncthreads();

        // --- fetch selected RAW x rows (exact x_sel) ---
        xselb[tid] = x[((size_t)(b0 + g) * S_DIM + isel[n]) * H_DIM + ss];
        __syncthreads();

        // --- VQ relative distances: d[n][p] = sum_k p*(p - 2x) ---
        float myd;
        {
            const float4* prow4 = reinterpret_cast<const float4*>(&pros[ss * PITCH]);
            const float4* xr4   = reinterpret_cast<const float4*>(&xselb[n * 64]);
            float d = 0.f;
#pragma unroll
            for (int k4 = 0; k4 < 16; ++k4) {
                float4 pv = prow4[k4], xv = xr4[k4];
                d += pv.x * (pv.x - 2.0f * xv.x);
                d += pv.y * (pv.y - 2.0f * xv.y);
                d += pv.z * (pv.z - 2.0f * xv.z);
                d += pv.w * (pv.w - 2.0f * xv.w);
            }
            myd = d;
        }

        // --- parallel argmin over p (first-min tie-break, matches jnp.argmin) ---
        {
            float v = myd; int idx = ss;
#pragma unroll
            for (int off = 16; off > 0; off >>= 1) {
                float ov = __shfl_xor_sync(0xFFFFFFFFu, v, off);
                int   oi = __shfl_xor_sync(0xFFFFFFFFu, idx, off);
                if (ov < v || (ov == v && oi < idx)) { v = ov; idx = oi; }
            }
            if ((tid & 31) == 0) { swred[wid] = v; swidx[wid] = idx; }
        }
        __syncthreads();
        if (tid < N_SEL) {
            float va = swred[2 * tid];     int ia = swidx[2 * tid];
            float vb = swred[2 * tid + 1]; int ib = swidx[2 * tid + 1];
            isel[N_SEL + tid] = (vb < va || (vb == va && ib < ia)) ? ib : ia;
        }
        __syncthreads();

        // --- outputs: proto_st / residuals (reference rounding preserved) ---
        {
            float xv  = xselb[tid];
            float pv  = pros[isel[N_SEL + n] * PITCH + ss];
            float d   = pv - xv;        // stop_grad(proto - x_sel)
            float pst = xv + d;         // proto_st
            size_t ob = (size_t)(b0 + g) * 256 + tid;
            out[ob]           = pst;
            out[OFF_RES + ob] = xv - pst;
            losspart += d * d;
        }
        __syncthreads();   // xselb/score reused next iteration
    }

    // --- deterministic block loss reduction ---
    red[tid] = losspart;
    __syncthreads();
#pragma unroll
    for (int st = 128; st > 0; st >>= 1) {
        if (tid < st) red[tid] += red[tid + st];
        __syncthreads();
    }
    if (tid == 0) g_partial[blockIdx.x] = red[0];

    // --- fused loss finalize: last block sums partials in fixed order ---
    __threadfence();
    if (tid == 0)
        amLast = (atomicAdd(&g_count, 1u) == (unsigned)(NBLKS - 1)) ? 1u : 0u;
    __syncthreads();
    if (amLast) {
        __threadfence();
        float s = 0.f;
        for (int i = tid; i < NBLKS; i += 256)   // fixed order -> deterministic
            s += g_partial[i];
        red[tid] = s;
        __syncthreads();
#pragma unroll
        for (int st = 128; st > 0; st >>= 1) {
            if (tid < st) red[tid] += red[tid + st];
            __syncthreads();
        }
        if (tid == 0) {
            out[OFF_LOSS] = red[0] * 1.25f / (float)(B_TOT * N_SEL * H_DIM);
            g_count = 0;                          // reset for next replay
        }
    }
}

// ---------------------------------------------------------------------------
extern "C" void kernel_launch(void* const* d_in, const int* in_sizes, int n_in,
                              void* d_out, int out_size) {
    (void)in_sizes; (void)n_in; (void)out_size;
    const float* x  = (const float*)d_in[0];
    const float* Wq = (const float*)d_in[1];
    const float* Wk = (const float*)d_in[2];
    const float* pr = (const float*)d_in[3];
    float* out = (float*)d_out;

    cudaFuncSetAttribute(main_kernel,
                         cudaFuncAttributeMaxDynamicSharedMemorySize, SMEM_BYTES);

    prep_kernel<<<260, 64>>>(Wq, Wk);
    main_kernel<<<NBLKS, 256, SMEM_BYTES>>>(x, pr, out);
}

// round 7
// speedup vs baseline: 1.2016x; 1.1711x over previous
#include <cuda_runtime.h>
#include <cstdint>

// Problem constants
#define B_TOT   4096
#define S_DIM   64
#define H_DIM   64
#define N_SEL   4
#define ATT_DIM 128
#define P_DIM   64

#define G_PER_BLK 4
#define NBLKS (B_TOT / G_PER_BLK)        // 1024
#define THREADS 1024
#define PITCH 68                          // smem row pitch (floats)

// Output layout (flatten-concat, float32):
#define OFF_RES  1048576u
#define OFF_LOSS 2097152u
#define OFF_IDX  2097153u

// Scratch (no allocations allowed -> device globals)
// M_t layout: g_M[(n*64 + k)*64 + h]  (k-major rows, h contiguous -> coalesced)
__device__ __align__(16) float g_M[N_SEL * H_DIM * H_DIM];
__device__ __align__(16) float g_pe[S_DIM * H_DIM];
__device__ float g_partial[NBLKS];
__device__ unsigned int g_count;          // zero-init; last block resets -> replay-safe

// ---------------------------------------------------------------------------
// Fused prep: blocks [0,256): M_t[n][k][h] = sum_a Wq[n,a,h]*Wk[n,a,k]
//             blocks [256,260): positional encoding (numpy-f32 rounding)
// ---------------------------------------------------------------------------
__global__ void prep_kernel(const float* __restrict__ Wq, const float* __restrict__ Wk) {
    if (blockIdx.x < 256) {
        int nk = blockIdx.x;
        int h  = threadIdx.x;
        int n  = nk >> 6;
        int k  = nk & 63;
        const float* wq = Wq + (size_t)n * ATT_DIM * H_DIM + h;   // lane-coalesced
        const float* wk = Wk + (size_t)n * ATT_DIM * H_DIM + k;   // broadcast
        float acc = 0.f;
#pragma unroll 8
        for (int a = 0; a < ATT_DIM; ++a)
            acc += wq[a * H_DIM] * wk[a * H_DIM];
        g_M[nk * 64 + h] = acc;           // [(n*64+k)*64 + h]
    } else {
        int base = (blockIdx.x - 256) * 1024;
        const float c = (float)(-0.14391156056944368);   // f32(-ln(1e4)/64)
#pragma unroll
        for (int k = 0; k < 16; ++k) {
            int idx = base + k * 64 + threadIdx.x;
            int s = idx >> 6, h = idx & 63;
            float arg  = (float)(h & ~1) * c;
            float divf = (float)exp((double)arg);
            float ang  = (float)s * divf;
            double sv  = (h & 1) ? cos((double)ang) : sin((double)ang);
            g_pe[idx] = (float)sv;
        }
    }
}

// ---------------------------------------------------------------------------
// threefry2x32, JAX partitionable mode: counter -> (0, gi), key (0,1),
// 32-bit draw = out0 ^ out1; uniform -> gumbel (bit-fidelity is load-bearing)
// ---------------------------------------------------------------------------
__device__ __forceinline__ uint32_t rotl32(uint32_t x, int d) {
    return (x << d) | (x >> (32 - d));
}

__device__ __forceinline__ float gumbel_at(uint32_t gi) {
    const uint32_t k0 = 0u, k1 = 1u, k2 = 0x1BD11BDBu;
    uint32_t x0 = 0u + k0;
    uint32_t x1 = gi + k1;
#define TF_ROUND(r) { x0 += x1; x1 = rotl32(x1, (r)); x1 ^= x0; }
    TF_ROUND(13) TF_ROUND(15) TF_ROUND(26) TF_ROUND(6)
    x0 += k1; x1 += k2 + 1u;
    TF_ROUND(17) TF_ROUND(29) TF_ROUND(16) TF_ROUND(24)
    x0 += k2; x1 += k0 + 2u;
    TF_ROUND(13) TF_ROUND(15) TF_ROUND(26) TF_ROUND(6)
    x0 += k0; x1 += k1 + 3u;
    TF_ROUND(17) TF_ROUND(29) TF_ROUND(16) TF_ROUND(24)
    x0 += k1; x1 += k2 + 4u;
    TF_ROUND(13) TF_ROUND(15) TF_ROUND(26) TF_ROUND(6)
    x0 += k2; x1 += k0 + 5u;
#undef TF_ROUND
    uint32_t bits = x0 ^ x1;
    uint32_t fb = (bits >> 9) | 0x3f800000u;
    float u = __uint_as_float(fb) - 1.0f;
    u = fmaxf(u, 1.17549435e-38f);
    return -logf(-logf(u));
}

// ---------------------------------------------------------------------------
// Main fused kernel: 1024 blocks x 1024 threads, 4 batches per block, all
// four batch-groups processed concurrently (phase-parallel, multicast layouts)
// ---------------------------------------------------------------------------
// smem floats: xs 4*64*68 | pros 64*68 | vs 16*68 | psumb 256 | part 1024 |
//              xsel 16*68 | candv 128 | candi 128(int) | isel 16 | psel 16
#define XS_F    (G_PER_BLK * S_DIM * PITCH)      // 17408
#define PROS_F  (P_DIM * PITCH)                  // 4352
#define VS_F    (16 * PITCH)                     // 1088
#define SMEM_FLOATS (XS_F + PROS_F + VS_F + 256 + 1024 + 16*PITCH + 128 + 128 + 32)
#define SMEM_BYTES  (SMEM_FLOATS * 4)

__global__ void __launch_bounds__(THREADS, 1) main_kernel(
    const float* __restrict__ x,
    const float* __restrict__ prototypes,
    float* __restrict__ out)
{
    extern __shared__ float sm[];
    float* xs    = sm;                       // [g][s][PITCH]
    float* pros  = xs + XS_F;                // [p][PITCH]
    float* vs    = pros + PROS_F;            // [(g*4+n)][PITCH]
    float* psumb = vs + VS_F;                // [g][64]
    float* part  = psumb + 256;              // [1024] psum partials / loss red
    float* xsel  = part + 1024;              // [(g*4+n)][PITCH]
    float* candv = xsel + 16 * PITCH;        // [128]
    int*   candi = (int*)(candv + 128);      // [128]
    int*   isel  = candi + 128;              // [16]
    int*   psel  = isel + 16;                // [16]
    __shared__ unsigned int amLast;

    const int tid  = threadIdx.x;
    const int lane = tid & 31;
    const int w    = tid >> 5;
    const int b0   = blockIdx.x * G_PER_BLK;

    // coords for (g, h)-style phases
    const int cg = tid >> 8;          // 0..3
    const int cn = (tid >> 6) & 3;    // 0..3
    const int ch = tid & 63;          // 0..63
    // coords for score/d2 phases (n minor -> 4-way row multicast)
    const int sg = tid >> 8;
    const int sp = (tid >> 2) & 63;   // s (score) or p (VQ)
    const int sn = tid & 3;

    // --- stage prototypes: exactly 1024 float4 ---
    {
        const float4* pp4 = reinterpret_cast<const float4*>(prototypes);
        int p  = tid >> 4;
        int k4 = tid & 15;
        *reinterpret_cast<float4*>(&pros[p * PITCH + k4 * 4]) = pp4[tid];
    }
    // --- stage pos = x + pe: 4096 float4 ---
    {
        const float4* xb4 = reinterpret_cast<const float4*>(x + (size_t)b0 * S_DIM * H_DIM);
        const float4* pe4 = reinterpret_cast<const float4*>(g_pe);
#pragma unroll
        for (int j = 0; j < 4; ++j) {
            int i4 = j * 1024 + tid;
            int g  = i4 >> 10;
            int s  = (i4 >> 4) & 63;
            int h4 = i4 & 15;
            float4 xv = xb4[i4];
            float4 pv = pe4[i4 & 1023];
            float4 o;
            o.x = xv.x + pv.x; o.y = xv.y + pv.y;
            o.z = xv.z + pv.z; o.w = xv.w + pv.w;
            *reinterpret_cast<float4*>(&xs[(g * 64 + s) * PITCH + h4 * 4]) = o;
        }
    }

    // one gumbel per thread, matching score-phase (g,n,s) coordinates
    float gnoise = gumbel_at((uint32_t)(b0 + sg) * 256u + (uint32_t)sn * 64u + (uint32_t)sp);

    __syncthreads();

    // --- psum partials: thread (g, q, h) sums 16 s-values ---
    {
        int q = (tid >> 6) & 3;
        const float* base = &xs[(cg * 64 + q * 16) * PITCH + ch];
        float ps = 0.f;
#pragma unroll
        for (int s16 = 0; s16 < 16; ++s16)
            ps += base[s16 * PITCH];
        part[tid] = ps;                 // [(g*4+q)*64 + h] == tid
    }
    __syncthreads();
    if (tid < 256) {
        int g = tid >> 6, h = tid & 63;
        psumb[tid] = part[g * 256 + h] + part[g * 256 + 64 + h]
                   + part[g * 256 + 128 + h] + part[g * 256 + 192 + h];
    }
    __syncthreads();

    // --- v[g][n][h] = (M_t[n][:,h] . psum[g]) / 512 : coalesced LDG ---
    {
        const float* Mt = g_M + (size_t)cn * 64 * 64 + ch;  // stride 64, lane-coalesced
        const float* pv = psumb + cg * 64;                  // broadcast
        float a = 0.f;
#pragma unroll 8
        for (int k = 0; k < 64; ++k)
            a += Mt[k * 64] * pv[k];
        vs[(cg * 4 + cn) * PITCH + ch] = a * (1.0f / 512.0f);
    }
    __syncthreads();

    // --- score[g][n][s] = pos[g][s] . v[g][n] + gumbel ---
    float myscore;
    {
        const float4* pr4 = reinterpret_cast<const float4*>(&xs[(sg * 64 + sp) * PITCH]);
        const float4* vr4 = reinterpret_cast<const float4*>(&vs[(sg * 4 + sn) * PITCH]);
        float lg = 0.f;
#pragma unroll
        for (int h4 = 0; h4 < 16; ++h4) {
            float4 a = pr4[h4], b = vr4[h4];
            lg += a.x * b.x + a.y * b.y + a.z * b.z + a.w * b.w;
        }
        myscore = lg + gnoise;
    }
    // argmax over s within warp (8 s-values per warp; lane = s_local*4 + n)
    {
        float v = myscore; int idx = sp;
#pragma unroll
        for (int off = 4; off <= 16; off <<= 1) {
            float ov = __shfl_xor_sync(0xFFFFFFFFu, v, off);
            int   oi = __shfl_xor_sync(0xFFFFFFFFu, idx, off);
            if (ov > v || (ov == v && oi < idx)) { v = ov; idx = oi; }
        }
        if (lane < 4) { candv[w * 4 + lane] = v; candi[w * 4 + lane] = idx; }
    }
    __syncthreads();
    if (tid < 16) {     // combine 8 warps per (g,n), first-max
        int g = tid >> 2, n = tid & 3;
        float best = candv[(g * 8) * 4 + n];
        int   bi   = candi[(g * 8) * 4 + n];
        for (int wb = 1; wb < 8; ++wb) {
            float v = candv[(g * 8 + wb) * 4 + n];
            int   i = candi[(g * 8 + wb) * 4 + n];
            if (v > best || (v == best && i < bi)) { best = v; bi = i; }
        }
        isel[tid] = bi;
        out[OFF_IDX + (size_t)(b0 + g) * N_SEL + n] = (float)bi;
    }
    __syncthreads();

    // --- gather selected raw x rows ---
    xsel[(cg * 4 + cn) * PITCH + ch] =
        x[((size_t)(b0 + cg) * S_DIM + isel[cg * 4 + cn]) * H_DIM + ch];
    __syncthreads();

    // --- VQ relative distance d[g][n][p] = pros[p].(pros[p] - 2*xsel[g][n]) ---
    float myd;
    {
        const float4* prow4 = reinterpret_cast<const float4*>(&pros[sp * PITCH]);
        const float4* xr4   = reinterpret_cast<const float4*>(&xsel[(sg * 4 + sn) * PITCH]);
        float d = 0.f;
#pragma unroll
        for (int k4 = 0; k4 < 16; ++k4) {
            float4 pv = prow4[k4], xv = xr4[k4];
            d += pv.x * (pv.x - 2.0f * xv.x);
            d += pv.y * (pv.y - 2.0f * xv.y);
            d += pv.z * (pv.z - 2.0f * xv.z);
            d += pv.w * (pv.w - 2.0f * xv.w);
        }
        myd = d;
    }
    {
        float v = myd; int idx = sp;
#pragma unroll
        for (int off = 4; off <= 16; off <<= 1) {
            float ov = __shfl_xor_sync(0xFFFFFFFFu, v, off);
            int   oi = __shfl_xor_sync(0xFFFFFFFFu, idx, off);
            if (ov < v || (ov == v && oi < idx)) { v = ov; idx = oi; }
        }
        if (lane < 4) { candv[w * 4 + lane] = v; candi[w * 4 + lane] = idx; }
    }
    __syncthreads();
    if (tid < 16) {     // combine, first-min
        int g = tid >> 2, n = tid & 3;
        float best = candv[(g * 8) * 4 + n];
        int   bi   = candi[(g * 8) * 4 + n];
        for (int wb = 1; wb < 8; ++wb) {
            float v = candv[(g * 8 + wb) * 4 + n];
            int   i = candi[(g * 8 + wb) * 4 + n];
            if (v < best || (v == best && i < bi)) { best = v; bi = i; }
        }
        psel[tid] = bi;
    }
    __syncthreads();

    // --- outputs (reference rounding preserved) + loss contribution ---
    float losspart;
    {
        float xv  = xsel[(cg * 4 + cn) * PITCH + ch];
        float pv  = pros[psel[cg * 4 + cn] * PITCH + ch];
        float d   = pv - xv;
        float pst = xv + d;
        size_t ob = (size_t)(b0 + cg) * 256 + (size_t)(tid & 255);
        out[ob]           = pst;
        out[OFF_RES + ob] = xv - pst;
        losspart = d * d;
    }

    // --- deterministic loss reduction (warp shuffle + smem combine) ---
    {
        float v = losspart;
#pragma unroll
        for (int off = 16; off > 0; off >>= 1)
            v += __shfl_xor_sync(0xFFFFFFFFu, v, off);
        if (lane == 0) part[w] = v;
    }
    __syncthreads();
    if (tid < 32) {
        float v = part[tid];
#pragma unroll
        for (int off = 16; off > 0; off >>= 1)
            v += __shfl_xor_sync(0xFFFFFFFFu, v, off);
        if (tid == 0) g_partial[blockIdx.x] = v;
    }

    // --- fused loss finalize: last block sums 1024 partials ---
    __threadfence();
    if (tid == 0)
        amLast = (atomicAdd(&g_count, 1u) == (unsigned)(NBLKS - 1)) ? 1u : 0u;
    __syncthreads();
    if (amLast) {
        __threadfence();
        float v = g_partial[tid];       // NBLKS == THREADS == 1024
#pragma unroll
        for (int off = 16; off > 0; off >>= 1)
            v += __shfl_xor_sync(0xFFFFFFFFu, v, off);
        if (lane == 0) part[w] = v;
        __syncthreads();
        if (tid < 32) {
            float s = part[tid];
#pragma unroll
            for (int off = 16; off > 0; off >>= 1)
                s += __shfl_xor_sync(0xFFFFFFFFu, s, off);
            if (tid == 0) {
                out[OFF_LOSS] = s * 1.25f / (float)(B_TOT * N_SEL * H_DIM);
                g_count = 0;            // reset for next graph replay
            }
        }
    }
}

// ---------------------------------------------------------------------------
extern "C" void kernel_launch(void* const* d_in, const int* in_sizes, int n_in,
                              void* d_out, int out_size) {
    (void)in_sizes; (void)n_in; (void)out_size;
    const float* x  = (const float*)d_in[0];
    const float* Wq = (const float*)d_in[1];
    const float* Wk = (const float*)d_in[2];
    const float* pr = (const float*)d_in[3];
    float* out = (float*)d_out;

    cudaFuncSetAttribute(main_kernel,
                         cudaFuncAttributeMaxDynamicSharedMemorySize, SMEM_BYTES);

    prep_kernel<<<260, 64>>>(Wq, Wk);
    main_kernel<<<NBLKS, THREADS, SMEM_BYTES>>>(x, pr, out);
}

// round 8
// speedup vs baseline: 1.3220x; 1.1002x over previous
#include <cuda_runtime.h>
#include <cstdint>

// Problem constants
#define B_TOT   4096
#define S_DIM   64
#define H_DIM   64
#define N_SEL   4
#define ATT_DIM 128
#define P_DIM   64

#define G_PER_BLK 4
#define NBLKS (B_TOT / G_PER_BLK)        // 1024
#define THREADS 1024
#define PITCH 68                          // smem row pitch (floats)

// Output layout (flatten-concat, float32):
#define OFF_RES  1048576u
#define OFF_LOSS 2097152u
#define OFF_IDX  2097153u

// Scratch (no allocations allowed -> device globals)
// M_t layout: g_M[(n*64 + k)*64 + h]  (k-major rows, h contiguous -> coalesced)
__device__ __align__(16) float g_M[N_SEL * H_DIM * H_DIM];
__device__ __align__(16) float g_pe[S_DIM * H_DIM];
__device__ float g_partial[NBLKS];
__device__ unsigned int g_count;          // zero-init; last block resets -> replay-safe

// ---------------------------------------------------------------------------
// Fused prep: blocks [0,256): M_t[n][k][h] = sum_a Wq[n,a,h]*Wk[n,a,k]
//             blocks [256,260): positional encoding (numpy-f32 rounding)
// ---------------------------------------------------------------------------
__global__ void prep_kernel(const float* __restrict__ Wq, const float* __restrict__ Wk) {
    if (blockIdx.x < 256) {
        int nk = blockIdx.x;
        int h  = threadIdx.x;
        int n  = nk >> 6;
        int k  = nk & 63;
        const float* wq = Wq + (size_t)n * ATT_DIM * H_DIM + h;   // lane-coalesced
        const float* wk = Wk + (size_t)n * ATT_DIM * H_DIM + k;   // broadcast
        float acc = 0.f;
#pragma unroll 8
        for (int a = 0; a < ATT_DIM; ++a)
            acc += wq[a * H_DIM] * wk[a * H_DIM];
        g_M[nk * 64 + h] = acc;           // [(n*64+k)*64 + h]
    } else {
        int base = (blockIdx.x - 256) * 1024;
        const float c = (float)(-0.14391156056944368);   // f32(-ln(1e4)/64)
#pragma unroll
        for (int k = 0; k < 16; ++k) {
            int idx = base + k * 64 + threadIdx.x;
            int s = idx >> 6, h = idx & 63;
            float arg  = (float)(h & ~1) * c;
            float divf = (float)exp((double)arg);
            float ang  = (float)s * divf;
            double sv  = (h & 1) ? cos((double)ang) : sin((double)ang);
            g_pe[idx] = (float)sv;
        }
    }
}

// ---------------------------------------------------------------------------
// threefry2x32, JAX partitionable mode: counter -> (0, gi), key (0,1),
// 32-bit draw = out0 ^ out1; uniform -> gumbel (bit-fidelity is load-bearing)
// ---------------------------------------------------------------------------
__device__ __forceinline__ uint32_t rotl32(uint32_t x, int d) {
    return (x << d) | (x >> (32 - d));
}

__device__ __forceinline__ float gumbel_at(uint32_t gi) {
    const uint32_t k0 = 0u, k1 = 1u, k2 = 0x1BD11BDBu;
    uint32_t x0 = 0u + k0;
    uint32_t x1 = gi + k1;
#define TF_ROUND(r) { x0 += x1; x1 = rotl32(x1, (r)); x1 ^= x0; }
    TF_ROUND(13) TF_ROUND(15) TF_ROUND(26) TF_ROUND(6)
    x0 += k1; x1 += k2 + 1u;
    TF_ROUND(17) TF_ROUND(29) TF_ROUND(16) TF_ROUND(24)
    x0 += k2; x1 += k0 + 2u;
    TF_ROUND(13) TF_ROUND(15) TF_ROUND(26) TF_ROUND(6)
    x0 += k0; x1 += k1 + 3u;
    TF_ROUND(17) TF_ROUND(29) TF_ROUND(16) TF_ROUND(24)
    x0 += k1; x1 += k2 + 4u;
    TF_ROUND(13) TF_ROUND(15) TF_ROUND(26) TF_ROUND(6)
    x0 += k2; x1 += k0 + 5u;
#undef TF_ROUND
    uint32_t bits = x0 ^ x1;
    uint32_t fb = (bits >> 9) | 0x3f800000u;
    float u = __uint_as_float(fb) - 1.0f;
    u = fmaxf(u, 1.17549435e-38f);
    return -logf(-logf(u));
}

// ---------------------------------------------------------------------------
// Main fused kernel: 1024 blocks x 1024 threads, 4 batches per block.
// v-phase reads M exactly once per block (amortized over the 4 groups).
// ---------------------------------------------------------------------------
#define XS_F    (G_PER_BLK * S_DIM * PITCH)      // 17408
#define PROS_F  (P_DIM * PITCH)                  // 4352
#define VS_F    (16 * PITCH)                     // 1088
#define PART_F  4096                              // k-quarter partials / reductions
#define SMEM_FLOATS (XS_F + PROS_F + VS_F + 256 + PART_F + 16*PITCH + 128 + 128 + 32)
#define SMEM_BYTES  (SMEM_FLOATS * 4)

__global__ void __launch_bounds__(THREADS, 1) main_kernel(
    const float* __restrict__ x,
    const float* __restrict__ prototypes,
    float* __restrict__ out)
{
    extern __shared__ float sm[];
    float* xs    = sm;                       // [g][s][PITCH]
    float* pros  = xs + XS_F;                // [p][PITCH]
    float* vs    = pros + PROS_F;            // [(g*4+n)][PITCH]
    float* psumb = vs + VS_F;                // [g][64]
    float* part  = psumb + 256;              // [4096]: psum partials / v partials / loss
    float* xsel  = part + PART_F;            // [(g*4+n)][PITCH]
    float* candv = xsel + 16 * PITCH;        // [128]
    int*   candi = (int*)(candv + 128);      // [128]
    int*   isel  = candi + 128;              // [16]
    int*   psel  = isel + 16;                // [16]
    __shared__ unsigned int amLast;

    const int tid  = threadIdx.x;
    const int lane = tid & 31;
    const int w    = tid >> 5;
    const int b0   = blockIdx.x * G_PER_BLK;

    // coords for (g, n, h)-style phases
    const int cg = tid >> 8;          // 0..3
    const int cn = (tid >> 6) & 3;    // 0..3
    const int ch = tid & 63;          // 0..63
    // coords for score/d2 phases (n minor -> 4-way row multicast)
    const int sg = tid >> 8;
    const int sp = (tid >> 2) & 63;   // s (score) or p (VQ)
    const int sn = tid & 3;

    // --- stage prototypes: exactly 1024 float4 ---
    {
        const float4* pp4 = reinterpret_cast<const float4*>(prototypes);
        int p  = tid >> 4;
        int k4 = tid & 15;
        *reinterpret_cast<float4*>(&pros[p * PITCH + k4 * 4]) = pp4[tid];
    }
    // --- stage pos = x + pe: 4096 float4 ---
    {
        const float4* xb4 = reinterpret_cast<const float4*>(x + (size_t)b0 * S_DIM * H_DIM);
        const float4* pe4 = reinterpret_cast<const float4*>(g_pe);
#pragma unroll
        for (int j = 0; j < 4; ++j) {
            int i4 = j * 1024 + tid;
            int g  = i4 >> 10;
            int s  = (i4 >> 4) & 63;
            int h4 = i4 & 15;
            float4 xv = xb4[i4];
            float4 pv = pe4[i4 & 1023];
            float4 o;
            o.x = xv.x + pv.x; o.y = xv.y + pv.y;
            o.z = xv.z + pv.z; o.w = xv.w + pv.w;
            *reinterpret_cast<float4*>(&xs[(g * 64 + s) * PITCH + h4 * 4]) = o;
        }
    }

    // one gumbel per thread, matching score-phase (g,n,s) coordinates
    float gnoise = gumbel_at((uint32_t)(b0 + sg) * 256u + (uint32_t)sn * 64u + (uint32_t)sp);

    __syncthreads();

    // --- psum partials: thread (g, q, h) sums 16 s-values ---
    {
        int q = (tid >> 6) & 3;
        const float* base = &xs[(cg * 64 + q * 16) * PITCH + ch];
        float ps = 0.f;
#pragma unroll
        for (int s16 = 0; s16 < 16; ++s16)
            ps += base[s16 * PITCH];
        part[tid] = ps;                 // [(g*4+q)*64 + h] == tid
    }
    __syncthreads();
    if (tid < 256) {
        int g = tid >> 6, h = tid & 63;
        psumb[tid] = part[g * 256 + h] + part[g * 256 + 64 + h]
                   + part[g * 256 + 128 + h] + part[g * 256 + 192 + h];
    }
    __syncthreads();

    // --- v partials: thread (n, k-quarter, h); M loaded ONCE per block,
    //     all 4 groups accumulated against float4-broadcast psum reads ---
    {
        const int vn = tid >> 8;          // 0..3
        const int vq = (tid >> 6) & 3;    // k-quarter
        const int vh = tid & 63;
        const float* Mt = g_M + ((size_t)(vn * 64 + vq * 16) * 64 + vh); // stride 64/k
        float a0 = 0.f, a1 = 0.f, a2 = 0.f, a3 = 0.f;
#pragma unroll
        for (int j = 0; j < 4; ++j) {
            float m0 = Mt[(j * 4 + 0) * 64];
            float m1 = Mt[(j * 4 + 1) * 64];
            float m2 = Mt[(j * 4 + 2) * 64];
            float m3 = Mt[(j * 4 + 3) * 64];
            float4 p0 = *reinterpret_cast<const float4*>(&psumb[  0 + vq * 16 + j * 4]);
            float4 p1 = *reinterpret_cast<const float4*>(&psumb[ 64 + vq * 16 + j * 4]);
            float4 p2 = *reinterpret_cast<const float4*>(&psumb[128 + vq * 16 + j * 4]);
            float4 p3 = *reinterpret_cast<const float4*>(&psumb[192 + vq * 16 + j * 4]);
            a0 += m0 * p0.x + m1 * p0.y + m2 * p0.z + m3 * p0.w;
            a1 += m0 * p1.x + m1 * p1.y + m2 * p1.z + m3 * p1.w;
            a2 += m0 * p2.x + m1 * p2.y + m2 * p2.z + m3 * p2.w;
            a3 += m0 * p3.x + m1 * p3.y + m2 * p3.z + m3 * p3.w;
        }
        int base = vq * 1024 + vn * 64 + vh;
        part[base +   0] = a0;            // [vq][(g*4+n)*64 + h], g=0..3
        part[base + 256] = a1;
        part[base + 512] = a2;
        part[base + 768] = a3;
    }
    __syncthreads();
    // --- combine k-quarters: tid == (g*4+n)*64 + h ---
    {
        float v = part[tid] + part[1024 + tid] + part[2048 + tid] + part[3072 + tid];
        vs[(cg * 4 + cn) * PITCH + ch] = v * (1.0f / 512.0f);
    }
    __syncthreads();

    // --- score[g][n][s] = pos[g][s] . v[g][n] + gumbel ---
    float myscore;
    {
        const float4* pr4 = reinterpret_cast<const float4*>(&xs[(sg * 64 + sp) * PITCH]);
        const float4* vr4 = reinterpret_cast<const float4*>(&vs[(sg * 4 + sn) * PITCH]);
        float lg = 0.f;
#pragma unroll
        for (int h4 = 0; h4 < 16; ++h4) {
            float4 a = pr4[h4], b = vr4[h4];
            lg += a.x * b.x + a.y * b.y + a.z * b.z + a.w * b.w;
        }
        myscore = lg + gnoise;
    }
    // argmax over s within warp (8 s-values per warp; lane = s_local*4 + n)
    {
        float v = myscore; int idx = sp;
#pragma unroll
        for (int off = 4; off <= 16; off <<= 1) {
            float ov = __shfl_xor_sync(0xFFFFFFFFu, v, off);
            int   oi = __shfl_xor_sync(0xFFFFFFFFu, idx, off);
            if (ov > v || (ov == v && oi < idx)) { v = ov; idx = oi; }
        }
        if (lane < 4) { candv[w * 4 + lane] = v; candi[w * 4 + lane] = idx; }
    }
    __syncthreads();
    if (tid < 16) {     // combine 8 warps per (g,n), first-max
        int g = tid >> 2, n = tid & 3;
        float best = candv[(g * 8) * 4 + n];
        int   bi   = candi[(g * 8) * 4 + n];
        for (int wb = 1; wb < 8; ++wb) {
            float v = candv[(g * 8 + wb) * 4 + n];
            int   i = candi[(g * 8 + wb) * 4 + n];
            if (v > best || (v == best && i < bi)) { best = v; bi = i; }
        }
        isel[tid] = bi;
        out[OFF_IDX + (size_t)(b0 + g) * N_SEL + n] = (float)bi;
    }
    __syncthreads();

    // --- gather selected raw x rows ---
    xsel[(cg * 4 + cn) * PITCH + ch] =
        x[((size_t)(b0 + cg) * S_DIM + isel[cg * 4 + cn]) * H_DIM + ch];
    __syncthreads();

    // --- VQ relative distance d[g][n][p] = pros[p].(pros[p] - 2*xsel[g][n]) ---
    float myd;
    {
        const float4* prow4 = reinterpret_cast<const float4*>(&pros[sp * PITCH]);
        const float4* xr4   = reinterpret_cast<const float4*>(&xsel[(sg * 4 + sn) * PITCH]);
        float d = 0.f;
#pragma unroll
        for (int k4 = 0; k4 < 16; ++k4) {
            float4 pv = prow4[k4], xv = xr4[k4];
            d += pv.x * (pv.x - 2.0f * xv.x);
            d += pv.y * (pv.y - 2.0f * xv.y);
            d += pv.z * (pv.z - 2.0f * xv.z);
            d += pv.w * (pv.w - 2.0f * xv.w);
        }
        myd = d;
    }
    {
        float v = myd; int idx = sp;
#pragma unroll
        for (int off = 4; off <= 16; off <<= 1) {
            float ov = __shfl_xor_sync(0xFFFFFFFFu, v, off);
            int   oi = __shfl_xor_sync(0xFFFFFFFFu, idx, off);
            if (ov < v || (ov == v && oi < idx)) { v = ov; idx = oi; }
        }
        if (lane < 4) { candv[w * 4 + lane] = v; candi[w * 4 + lane] = idx; }
    }
    __syncthreads();
    if (tid < 16) {     // combine, first-min
        int g = tid >> 2, n = tid & 3;
        float best = candv[(g * 8) * 4 + n];
        int   bi   = candi[(g * 8) * 4 + n];
        for (int wb = 1; wb < 8; ++wb) {
            float v = candv[(g * 8 + wb) * 4 + n];
            int   i = candi[(g * 8 + wb) * 4 + n];
            if (v < best || (v == best && i < bi)) { best = v; bi = i; }
        }
        psel[tid] = bi;
    }
    __syncthreads();

    // --- outputs (reference rounding preserved) + loss contribution ---
    float losspart;
    {
        float xv  = xsel[(cg * 4 + cn) * PITCH + ch];
        float pv  = pros[psel[cg * 4 + cn] * PITCH + ch];
        float d   = pv - xv;
        float pst = xv + d;
        size_t ob = (size_t)(b0 + cg) * 256 + (size_t)(tid & 255);
        out[ob]           = pst;
        out[OFF_RES + ob] = xv - pst;
        losspart = d * d;
    }

    // --- deterministic loss reduction (warp shuffle + smem combine) ---
    {
        float v = losspart;
#pragma unroll
        for (int off = 16; off > 0; off >>= 1)
            v += __shfl_xor_sync(0xFFFFFFFFu, v, off);
        if (lane == 0) part[w] = v;
    }
    __syncthreads();
    if (tid < 32) {
        float v = part[tid];
#pragma unroll
        for (int off = 16; off > 0; off >>= 1)
            v += __shfl_xor_sync(0xFFFFFFFFu, v, off);
        if (tid == 0) g_partial[blockIdx.x] = v;
    }

    // --- fused loss finalize: last block sums 1024 partials ---
    __threadfence();
    if (tid == 0)
        amLast = (atomicAdd(&g_count, 1u) == (unsigned)(NBLKS - 1)) ? 1u : 0u;
    __syncthreads();
    if (amLast) {
        __threadfence();
        float v = g_partial[tid];       // NBLKS == THREADS == 1024
#pragma unroll
        for (int off = 16; off > 0; off >>= 1)
            v += __shfl_xor_sync(0xFFFFFFFFu, v, off);
        if (lane == 0) part[w] = v;
        __syncthreads();
        if (tid < 32) {
            float s = part[tid];
#pragma unroll
            for (int off = 16; off > 0; off >>= 1)
                s += __shfl_xor_sync(0xFFFFFFFFu, s, off);
            if (tid == 0) {
                out[OFF_LOSS] = s * 1.25f / (float)(B_TOT * N_SEL * H_DIM);
                g_count = 0;            // reset for next graph replay
            }
        }
    }
}

// ---------------------------------------------------------------------------
extern "C" void kernel_launch(void* const* d_in, const int* in_sizes, int n_in,
                              void* d_out, int out_size) {
    (void)in_sizes; (void)n_in; (void)out_size;
    const float* x  = (const float*)d_in[0];
    const float* Wq = (const float*)d_in[1];
    const float* Wk = (const float*)d_in[2];
    const float* pr = (const float*)d_in[3];
    float* out = (float*)d_out;

    cudaFuncSetAttribute(main_kernel,
                         cudaFuncAttributeMaxDynamicSharedMemorySize, SMEM_BYTES);

    prep_kernel<<<260, 64>>>(Wq, Wk);
    main_kernel<<<NBLKS, THREADS, SMEM_BYTES>>>(x, pr, out);
}

// round 9
// speedup vs baseline: 1.4076x; 1.0647x over previous
#include <cuda_runtime.h>
#include <cstdint>

// Problem constants
#define B_TOT   4096
#define S_DIM   64
#define H_DIM   64
#define N_SEL   4
#define ATT_DIM 128
#define P_DIM   64

#define G_PER_BLK 2
#define NBLKS (B_TOT / G_PER_BLK)        // 2048
#define THREADS 512
#define PITCH 68                          // smem row pitch (floats)

// Output layout (flatten-concat, float32):
#define OFF_RES  1048576u
#define OFF_LOSS 2097152u
#define OFF_IDX  2097153u

// Scratch (no allocations allowed -> device globals)
// M_t layout: g_M[(n*64 + k)*64 + h]  (k-major rows, h contiguous -> coalesced)
__device__ __align__(16) float g_M[N_SEL * H_DIM * H_DIM];
__device__ __align__(16) float g_pe[S_DIM * H_DIM];
__device__ float g_partial[NBLKS];
__device__ unsigned int g_count;          // zero-init; last block resets -> replay-safe

// ---------------------------------------------------------------------------
// Fused prep: blocks [0,256): M_t[n][k][h] = sum_a Wq[n,a,h]*Wk[n,a,k]
//             blocks [256,260): positional encoding (numpy-f32 rounding)
// ---------------------------------------------------------------------------
__global__ void prep_kernel(const float* __restrict__ Wq, const float* __restrict__ Wk) {
    if (blockIdx.x < 256) {
        int nk = blockIdx.x;
        int h  = threadIdx.x;
        int n  = nk >> 6;
        int k  = nk & 63;
        const float* wq = Wq + (size_t)n * ATT_DIM * H_DIM + h;   // lane-coalesced
        const float* wk = Wk + (size_t)n * ATT_DIM * H_DIM + k;   // broadcast
        float acc = 0.f;
#pragma unroll 8
        for (int a = 0; a < ATT_DIM; ++a)
            acc += wq[a * H_DIM] * wk[a * H_DIM];
        g_M[nk * 64 + h] = acc;           // [(n*64+k)*64 + h]
    } else {
        int base = (blockIdx.x - 256) * 1024;
        const float c = (float)(-0.14391156056944368);   // f32(-ln(1e4)/64)
#pragma unroll
        for (int k = 0; k < 16; ++k) {
            int idx = base + k * 64 + threadIdx.x;
            int s = idx >> 6, h = idx & 63;
            float arg  = (float)(h & ~1) * c;
            float divf = (float)exp((double)arg);
            float ang  = (float)s * divf;
            double sv  = (h & 1) ? cos((double)ang) : sin((double)ang);
            g_pe[idx] = (float)sv;
        }
    }
}

// ---------------------------------------------------------------------------
// threefry2x32, JAX partitionable mode: counter -> (0, gi), key (0,1),
// 32-bit draw = out0 ^ out1; uniform -> gumbel (bit-fidelity is load-bearing)
// ---------------------------------------------------------------------------
__device__ __forceinline__ uint32_t rotl32(uint32_t x, int d) {
    return (x << d) | (x >> (32 - d));
}

__device__ __forceinline__ float gumbel_at(uint32_t gi) {
    const uint32_t k0 = 0u, k1 = 1u, k2 = 0x1BD11BDBu;
    uint32_t x0 = 0u + k0;
    uint32_t x1 = gi + k1;
#define TF_ROUND(r) { x0 += x1; x1 = rotl32(x1, (r)); x1 ^= x0; }
    TF_ROUND(13) TF_ROUND(15) TF_ROUND(26) TF_ROUND(6)
    x0 += k1; x1 += k2 + 1u;
    TF_ROUND(17) TF_ROUND(29) TF_ROUND(16) TF_ROUND(24)
    x0 += k2; x1 += k0 + 2u;
    TF_ROUND(13) TF_ROUND(15) TF_ROUND(26) TF_ROUND(6)
    x0 += k0; x1 += k1 + 3u;
    TF_ROUND(17) TF_ROUND(29) TF_ROUND(16) TF_ROUND(24)
    x0 += k1; x1 += k2 + 4u;
    TF_ROUND(13) TF_ROUND(15) TF_ROUND(26) TF_ROUND(6)
    x0 += k2; x1 += k0 + 5u;
#undef TF_ROUND
    uint32_t bits = x0 ^ x1;
    uint32_t fb = (bits >> 9) | 0x3f800000u;
    float u = __uint_as_float(fb) - 1.0f;
    u = fmaxf(u, 1.17549435e-38f);
    return -logf(-logf(u));
}

// ---------------------------------------------------------------------------
// Main fused kernel: 2048 blocks x 512 threads, 2 batches per block,
// 2 CTAs co-resident per SM to overlap the serial phase chains.
// ---------------------------------------------------------------------------
#define XS_F    (G_PER_BLK * S_DIM * PITCH)      // 8704
#define PROS_F  (P_DIM * PITCH)                  // 4352
#define VS_F    (8 * PITCH)                      // 544
#define PART_F  1024                              // partial buffers / reductions
#define SMEM_FLOATS (XS_F + PROS_F + VS_F + 128 + PART_F + 8*PITCH + 64 + 64 + 24)
#define SMEM_BYTES  (SMEM_FLOATS * 4)

__global__ void __launch_bounds__(THREADS, 2) main_kernel(
    const float* __restrict__ x,
    const float* __restrict__ prototypes,
    float* __restrict__ out)
{
    extern __shared__ float sm[];
    float* xs    = sm;                       // [g][s][PITCH]            g=0..1
    float* pros  = xs + XS_F;                // [p][PITCH]
    float* vs    = pros + PROS_F;            // [(g*4+n)][PITCH]         8 rows
    float* psumb = vs + VS_F;                // [g][64]                  128
    float* part  = psumb + 128;              // [1024] partials / reductions
    float* xsel  = part + PART_F;            // [(g*4+n)][PITCH]         8 rows
    float* candv = xsel + 8 * PITCH;         // [64]  (16 warps x 4)
    int*   candi = (int*)(candv + 64);       // [64]
    int*   isel  = candi + 64;               // [8]
    int*   psel  = isel + 8;                 // [8]
    __shared__ unsigned int amLast;

    const int tid  = threadIdx.x;
    const int lane = tid & 31;
    const int w    = tid >> 5;
    const int b0   = blockIdx.x * G_PER_BLK;

    // coords for (g, n, h)-style phases
    const int cg = tid >> 8;          // 0..1
    const int cn = (tid >> 6) & 3;    // 0..3
    const int ch = tid & 63;          // 0..63
    // coords for score/d2 phases (n minor -> 4-way row multicast)
    const int sg = tid >> 8;          // 0..1
    const int sp = (tid >> 2) & 63;   // s (score) or p (VQ)
    const int sn = tid & 3;

    // --- stage prototypes: 1024 float4 over 512 threads ---
    {
        const float4* pp4 = reinterpret_cast<const float4*>(prototypes);
#pragma unroll
        for (int j = 0; j < 2; ++j) {
            int i4 = j * 512 + tid;
            int p  = i4 >> 4;
            int k4 = i4 & 15;
            *reinterpret_cast<float4*>(&pros[p * PITCH + k4 * 4]) = pp4[i4];
        }
    }
    // --- stage pos = x + pe: 2048 float4 ---
    {
        const float4* xb4 = reinterpret_cast<const float4*>(x + (size_t)b0 * S_DIM * H_DIM);
        const float4* pe4 = reinterpret_cast<const float4*>(g_pe);
#pragma unroll
        for (int j = 0; j < 4; ++j) {
            int i4 = j * 512 + tid;
            int g  = i4 >> 10;
            int s  = (i4 >> 4) & 63;
            int h4 = i4 & 15;
            float4 xv = xb4[i4];
            float4 pv = pe4[i4 & 1023];
            float4 o;
            o.x = xv.x + pv.x; o.y = xv.y + pv.y;
            o.z = xv.z + pv.z; o.w = xv.w + pv.w;
            *reinterpret_cast<float4*>(&xs[(g * 64 + s) * PITCH + h4 * 4]) = o;
        }
    }

    // one gumbel per thread, matching score-phase (g,n,s) coordinates
    float gnoise = gumbel_at((uint32_t)(b0 + sg) * 256u + (uint32_t)sn * 64u + (uint32_t)sp);

    __syncthreads();

    // --- psum partials: thread (g, q, h) sums 16 s-values ---
    {
        int q = (tid >> 6) & 3;
        const float* base = &xs[(cg * 64 + q * 16) * PITCH + ch];
        float ps = 0.f;
#pragma unroll
        for (int s16 = 0; s16 < 16; ++s16)
            ps += base[s16 * PITCH];
        part[tid] = ps;                 // [(g*4+q)*64 + h] == tid
    }
    __syncthreads();
    if (tid < 128) {
        int g = tid >> 6, h = tid & 63;
        psumb[tid] = part[g * 256 + h] + part[g * 256 + 64 + h]
                   + part[g * 256 + 128 + h] + part[g * 256 + 192 + h];
    }
    __syncthreads();

    // --- v partials: thread (n, k-half, h); M loaded ONCE per block,
    //     both groups accumulated against float4-broadcast psum reads ---
    {
        const int vn = tid >> 7;          // 0..3
        const int vq = (tid >> 6) & 1;    // k-half
        const int vh = tid & 63;
        const float* Mt = g_M + ((size_t)(vn * 64 + vq * 32) * 64 + vh);
        float a0 = 0.f, a1 = 0.f;
#pragma unroll
        for (int j = 0; j < 8; ++j) {
            float m0 = Mt[(j * 4 + 0) * 64];
            float m1 = Mt[(j * 4 + 1) * 64];
            float m2 = Mt[(j * 4 + 2) * 64];
            float m3 = Mt[(j * 4 + 3) * 64];
            float4 p0 = *reinterpret_cast<const float4*>(&psumb[ 0 + vq * 32 + j * 4]);
            float4 p1 = *reinterpret_cast<const float4*>(&psumb[64 + vq * 32 + j * 4]);
            a0 += m0 * p0.x + m1 * p0.y + m2 * p0.z + m3 * p0.w;
            a1 += m0 * p1.x + m1 * p1.y + m2 * p1.z + m3 * p1.w;
        }
        int base = vq * 512 + vn * 64 + vh;
        part[base +   0] = a0;            // [vq][(g*4+n)*64 + h], g=0..1
        part[base + 256] = a1;
    }
    __syncthreads();
    // --- combine k-halves: tid == (g*4+n)*64 + h ---
    {
        float v = part[tid] + part[512 + tid];
        vs[(cg * 4 + cn) * PITCH + ch] = v * (1.0f / 512.0f);
    }
    __syncthreads();

    // --- score[g][n][s] = pos[g][s] . v[g][n] + gumbel ---
    float myscore;
    {
        const float4* pr4 = reinterpret_cast<const float4*>(&xs[(sg * 64 + sp) * PITCH]);
        const float4* vr4 = reinterpret_cast<const float4*>(&vs[(sg * 4 + sn) * PITCH]);
        float lg = 0.f;
#pragma unroll
        for (int h4 = 0; h4 < 16; ++h4) {
            float4 a = pr4[h4], b = vr4[h4];
            lg += a.x * b.x + a.y * b.y + a.z * b.z + a.w * b.w;
        }
        myscore = lg + gnoise;
    }
    // argmax over s within warp (8 s-values per warp; lane = s_local*4 + n)
    {
        float v = myscore; int idx = sp;
#pragma unroll
        for (int off = 4; off <= 16; off <<= 1) {
            float ov = __shfl_xor_sync(0xFFFFFFFFu, v, off);
            int   oi = __shfl_xor_sync(0xFFFFFFFFu, idx, off);
            if (ov > v || (ov == v && oi < idx)) { v = ov; idx = oi; }
        }
        if (lane < 4) { candv[w * 4 + lane] = v; candi[w * 4 + lane] = idx; }
    }
    __syncthreads();
    if (tid < 8) {      // combine 8 warps per (g,n), first-max
        int g = tid >> 2, n = tid & 3;
        float best = candv[(g * 8) * 4 + n];
        int   bi   = candi[(g * 8) * 4 + n];
        for (int wb = 1; wb < 8; ++wb) {
            float v = candv[(g * 8 + wb) * 4 + n];
            int   i = candi[(g * 8 + wb) * 4 + n];
            if (v > best || (v == best && i < bi)) { best = v; bi = i; }
        }
        isel[tid] = bi;
        out[OFF_IDX + (size_t)(b0 + g) * N_SEL + n] = (float)bi;
    }
    __syncthreads();

    // --- gather selected raw x rows ---
    xsel[(cg * 4 + cn) * PITCH + ch] =
        x[((size_t)(b0 + cg) * S_DIM + isel[cg * 4 + cn]) * H_DIM + ch];
    __syncthreads();

    // --- VQ relative distance d[g][n][p] = pros[p].(pros[p] - 2*xsel[g][n]) ---
    float myd;
    {
        const float4* prow4 = reinterpret_cast<const float4*>(&pros[sp * PITCH]);
        const float4* xr4   = reinterpret_cast<const float4*>(&xsel[(sg * 4 + sn) * PITCH]);
        float d = 0.f;
#pragma unroll
        for (int k4 = 0; k4 < 16; ++k4) {
            float4 pv = prow4[k4], xv = xr4[k4];
            d += pv.x * (pv.x - 2.0f * xv.x);
            d += pv.y * (pv.y - 2.0f * xv.y);
            d += pv.z * (pv.z - 2.0f * xv.z);
            d += pv.w * (pv.w - 2.0f * xv.w);
        }
        myd = d;
    }
    {
        float v = myd; int idx = sp;
#pragma unroll
        for (int off = 4; off <= 16; off <<= 1) {
            float ov = __shfl_xor_sync(0xFFFFFFFFu, v, off);
            int   oi = __shfl_xor_sync(0xFFFFFFFFu, idx, off);
            if (ov < v || (ov == v && oi < idx)) { v = ov; idx = oi; }
        }
        if (lane < 4) { candv[w * 4 + lane] = v; candi[w * 4 + lane] = idx; }
    }
    __syncthreads();
    if (tid < 8) {      // combine, first-min
        int g = tid >> 2, n = tid & 3;
        float best = candv[(g * 8) * 4 + n];
        int   bi   = candi[(g * 8) * 4 + n];
        for (int wb = 1; wb < 8; ++wb) {
            float v = candv[(g * 8 + wb) * 4 + n];
            int   i = candi[(g * 8 + wb) * 4 + n];
            if (v < best || (v == best && i < bi)) { best = v; bi = i; }
        }
        psel[tid] = bi;
    }
    __syncthreads();

    // --- outputs (reference rounding preserved) + loss contribution ---
    float losspart;
    {
        float xv  = xsel[(cg * 4 + cn) * PITCH + ch];
        float pv  = pros[psel[cg * 4 + cn] * PITCH + ch];
        float d   = pv - xv;
        float pst = xv + d;
        size_t ob = (size_t)(b0 + cg) * 256 + (size_t)(tid & 255);
        out[ob]           = pst;
        out[OFF_RES + ob] = xv - pst;
        losspart = d * d;
    }

    // --- deterministic loss reduction (warp shuffle + smem combine) ---
    {
        float v = losspart;
#pragma unroll
        for (int off = 16; off > 0; off >>= 1)
            v += __shfl_xor_sync(0xFFFFFFFFu, v, off);
        if (lane == 0) part[w] = v;
    }
    __syncthreads();
    if (tid < 32) {
        float v = (tid < 16) ? part[tid] : 0.f;
#pragma unroll
        for (int off = 16; off > 0; off >>= 1)
            v += __shfl_xor_sync(0xFFFFFFFFu, v, off);
        if (tid == 0) g_partial[blockIdx.x] = v;
    }

    // --- fused loss finalize: last block sums 2048 partials ---
    __threadfence();
    if (tid == 0)
        amLast = (atomicAdd(&g_count, 1u) == (unsigned)(NBLKS - 1)) ? 1u : 0u;
    __syncthreads();
    if (amLast) {
        __threadfence();
        float v = g_partial[tid] + g_partial[512 + tid]
                + g_partial[1024 + tid] + g_partial[1536 + tid];
#pragma unroll
        for (int off = 16; off > 0; off >>= 1)
            v += __shfl_xor_sync(0xFFFFFFFFu, v, off);
        if (lane == 0) part[w] = v;
        __syncthreads();
        if (tid < 32) {
            float s = (tid < 16) ? part[tid] : 0.f;
#pragma unroll
            for (int off = 16; off > 0; off >>= 1)
                s += __shfl_xor_sync(0xFFFFFFFFu, s, off);
            if (tid == 0) {
                out[OFF_LOSS] = s * 1.25f / (float)(B_TOT * N_SEL * H_DIM);
                g_count = 0;            // reset for next graph replay
            }
        }
    }
}

// ---------------------------------------------------------------------------
extern "C" void kernel_launch(void* const* d_in, const int* in_sizes, int n_in,
                              void* d_out, int out_size) {
    (void)in_sizes; (void)n_in; (void)out_size;
    const float* x  = (const float*)d_in[0];
    const float* Wq = (const float*)d_in[1];
    const float* Wk = (const float*)d_in[2];
    const float* pr = (const float*)d_in[3];
    float* out = (float*)d_out;

    cudaFuncSetAttribute(main_kernel,
                         cudaFuncAttributeMaxDynamicSharedMemorySize, SMEM_BYTES);

    prep_kernel<<<260, 64>>>(Wq, Wk);
    main_kernel<<<NBLKS, THREADS, SMEM_BYTES>>>(x, pr, out);
}